// round 8
// baseline (speedup 1.0000x reference)
#include <cuda_runtime.h>
#include <cuda_bf16.h>
#include <math.h>
#include <stdint.h>

#define BB 2
#define TT 2048
#define CC 1024
#define HH 16
#define DD 64
#define MM (BB*TT)      // 4096
#define QTILES (TT/64)  // 32

// Scratch (device globals: allocation-free, graph-capture safe)
__device__ float g_Q[BB*HH*TT*DD];
__device__ float g_K[BB*HH*TT*DD];
__device__ float g_V[BB*HH*TT*DD];
__device__ float g_Y[BB*HH*TT*DD];
__device__ float g_Yn[MM*CC];             // GroupNorm-applied Y, [m][k]
__device__ float g_part[BB*HH*QTILES*2];
__device__ float g_norm[BB*HH*2];

// ===========================================================================
// mma.sync bf16 (baseline ISA, works on sm_103 non-'a' target)
// D[16x8] += A[16x16] * B[16x8], A row-major, B col-major (K-contig both)
// ===========================================================================
__device__ __forceinline__ void mma16816(float d[4], const uint32_t a[4],
                                         const uint32_t b[2]) {
    asm volatile(
        "mma.sync.aligned.m16n8k16.row.col.f32.bf16.bf16.f32 "
        "{%0,%1,%2,%3}, {%4,%5,%6,%7}, {%8,%9}, {%0,%1,%2,%3};"
        : "+f"(d[0]), "+f"(d[1]), "+f"(d[2]), "+f"(d[3])
        : "r"(a[0]), "r"(a[1]), "r"(a[2]), "r"(a[3]), "r"(b[0]), "r"(b[1]));
}

// fp32 -> (bf16 hi, bf16 lo) split: a = hi + lo + O(2^-17 * a)
__device__ __forceinline__ void cvt_pair(float a, float b, uint32_t& hi, uint32_t& lo) {
    __nv_bfloat162 h, l;
    h.x = __float2bfloat16(a); h.y = __float2bfloat16(b);
    l.x = __float2bfloat16(a - __bfloat162float(h.x));
    l.y = __float2bfloat16(b - __bfloat162float(h.y));
    hi = *(uint32_t*)&h; lo = *(uint32_t*)&l;
}

// ===========================================================================
// Split-bf16 tensor-core GEMM: D[m,n] = sum_k A[m,k] * W[n,k]
// CTA tile 128x128, K-chunk 64, 256 threads (8 warps, 4x2), warp tile 32x64.
// mode 0/1/2: scatter to g_Q/g_K/g_V (B,H,T,D) with scale; mode 3: direct out.
// SMEM rows padded to 72 bf16 (144B) -> conflict-free fragment loads.
// ===========================================================================
#define KCH 64
#define STR 72
#define TILE_U (128*STR)                 // bf16 units per tile
#define GEMM_SMEM (4*TILE_U*2)           // 73728 B

__global__ void __launch_bounds__(256, 1)
gemm_kernel(const float* __restrict__ A, const float* __restrict__ W,
            float* __restrict__ OutDirect, int mode, float scale) {
    extern __shared__ __nv_bfloat16 smB[];
    __nv_bfloat16* Ahi = smB;
    __nv_bfloat16* Alo = smB + TILE_U;
    __nv_bfloat16* Bhi = smB + 2*TILE_U;
    __nv_bfloat16* Blo = smB + 3*TILE_U;

    int tid = threadIdx.x;
    int wid = tid >> 5, lane = tid & 31;
    int g = lane >> 2, tg = lane & 3;
    int wm = wid >> 1, wn = wid & 1;             // 4x2 warp grid
    int m0 = blockIdx.x * 128, n0 = blockIdx.y * 128;

    const float* Ap = A ? A : g_Yn;
    int lrow = tid >> 1, lhalf = (tid & 1) * 32; // loader: row, 32-col half
    const float* Arow = Ap + (size_t)(m0 + lrow) * CC + lhalf;
    const float* Brow = W  + (size_t)(n0 + lrow) * CC + lhalf;

    float acc[2][8][4] = {};

    for (int k0 = 0; k0 < CC; k0 += KCH) {
        // ---- load + split-convert chunk (each thread: 32 A elems + 32 B) ----
        #pragma unroll
        for (int j = 0; j < 8; j++) {
            float4 a = *(const float4*)(Arow + k0 + j*4);
            uint32_t h0, l0, h1, l1;
            cvt_pair(a.x, a.y, h0, l0); cvt_pair(a.z, a.w, h1, l1);
            int u = lrow*STR + lhalf + j*4;
            *(uint2*)(Ahi + u) = make_uint2(h0, h1);
            *(uint2*)(Alo + u) = make_uint2(l0, l1);

            float4 b = *(const float4*)(Brow + k0 + j*4);
            cvt_pair(b.x, b.y, h0, l0); cvt_pair(b.z, b.w, h1, l1);
            *(uint2*)(Bhi + u) = make_uint2(h0, h1);
            *(uint2*)(Blo + u) = make_uint2(l0, l1);
        }
        __syncthreads();

        // ---- 4 k-steps of 16 ----
        #pragma unroll
        for (int ks = 0; ks < 4; ks++) {
            int kc = ks*16 + tg*2;
            uint32_t ah[2][4], al[2][4];
            #pragma unroll
            for (int mf = 0; mf < 2; mf++) {
                int r = wm*32 + mf*16 + g;
                ah[mf][0] = *(const uint32_t*)(Ahi + (r  )*STR + kc);
                ah[mf][1] = *(const uint32_t*)(Ahi + (r+8)*STR + kc);
                ah[mf][2] = *(const uint32_t*)(Ahi + (r  )*STR + kc + 8);
                ah[mf][3] = *(const uint32_t*)(Ahi + (r+8)*STR + kc + 8);
                al[mf][0] = *(const uint32_t*)(Alo + (r  )*STR + kc);
                al[mf][1] = *(const uint32_t*)(Alo + (r+8)*STR + kc);
                al[mf][2] = *(const uint32_t*)(Alo + (r  )*STR + kc + 8);
                al[mf][3] = *(const uint32_t*)(Alo + (r+8)*STR + kc + 8);
            }
            #pragma unroll
            for (int nf = 0; nf < 8; nf++) {
                int n = wn*64 + nf*8 + g;
                uint32_t bh[2], bl[2];
                bh[0] = *(const uint32_t*)(Bhi + n*STR + kc);
                bh[1] = *(const uint32_t*)(Bhi + n*STR + kc + 8);
                bl[0] = *(const uint32_t*)(Blo + n*STR + kc);
                bl[1] = *(const uint32_t*)(Blo + n*STR + kc + 8);
                #pragma unroll
                for (int mf = 0; mf < 2; mf++) {
                    mma16816(acc[mf][nf], ah[mf], bh);   // hi*hi
                    mma16816(acc[mf][nf], ah[mf], bl);   // hi*lo
                    mma16816(acc[mf][nf], al[mf], bh);   // lo*hi
                }
            }
        }
        __syncthreads();
    }

    // ---- epilogue: direct stores (each 4-lane group fills a 32B sector) ----
    if (mode == 3) {
        #pragma unroll
        for (int mf = 0; mf < 2; mf++) {
            int m = m0 + wm*32 + mf*16 + g;
            #pragma unroll
            for (int nf = 0; nf < 8; nf++) {
                int n = n0 + wn*64 + nf*8 + tg*2;
                float* d = acc[mf][nf];
                *(float2*)(OutDirect + (size_t)m*CC + n)     = make_float2(d[0], d[1]);
                *(float2*)(OutDirect + (size_t)(m+8)*CC + n) = make_float2(d[2], d[3]);
            }
        }
    } else {
        float* Out = (mode == 0) ? g_Q : (mode == 1) ? g_K : g_V;
        #pragma unroll
        for (int mf = 0; mf < 2; mf++) {
            int m = m0 + wm*32 + mf*16 + g;
            int b = m >> 11, t = m & (TT - 1);
            #pragma unroll
            for (int nf = 0; nf < 8; nf++) {
                int n = n0 + wn*64 + nf*8 + tg*2;
                int h = n >> 6, d0 = n & 63;
                float* d = acc[mf][nf];
                size_t base = ((size_t)(b*HH + h)*TT);
                *(float2*)(Out + (base + t  )*DD + d0) = make_float2(d[0]*scale, d[1]*scale);
                *(float2*)(Out + (base + t+8)*DD + d0) = make_float2(d[2]*scale, d[3]*scale);
            }
        }
    }
}

// ---------------------------------------------------------------------------
// Retention (unchanged from R6 passing version)
// ---------------------------------------------------------------------------
__global__ void retention_kernel() {
    extern __shared__ float sm[];
    float* Qs = sm;
    float* Ks = sm + 4096;
    float* Vs = sm + 8192;
    float* Ss = sm + 12288;

    int tid = threadIdx.x;
    int qt = blockIdx.x, bh = blockIdx.y;
    int h = bh & (HH - 1);
    size_t base = (size_t)bh * TT * DD;
    int i0 = qt * 64;

    float gamma = 1.0f - exp2f(-5.0f - 0.5f * (float)h);
    float lg = log2f(gamma);

    int tr = tid >> 4, tc = tid & 15;
    int lr = tid >> 2, lk = (tid & 3) << 2;

    #pragma unroll
    for (int cch = 0; cch < 4; cch++) {
        int col = lk + cch*16;
        float4 q = *(const float4*)(g_Q + base + (size_t)(i0 + lr)*DD + col);
        Qs[(col+0)*64+lr]=q.x; Qs[(col+1)*64+lr]=q.y;
        Qs[(col+2)*64+lr]=q.z; Qs[(col+3)*64+lr]=q.w;
    }

    float acc[4][4] = {};

    for (int j0 = 0; j0 <= i0; j0 += 64) {
        int dist = i0 - j0;
        bool diag = (dist == 0);

        float cc = diag ? 1.0f : exp2f((float)(63 - lr) * lg);
        #pragma unroll
        for (int cch = 0; cch < 4; cch++) {
            int col = lk + cch*16;
            float4 kv = *(const float4*)(g_K + base + (size_t)(j0 + lr)*DD + col);
            Ks[(col+0)*64+lr]=kv.x*cc; Ks[(col+1)*64+lr]=kv.y*cc;
            Ks[(col+2)*64+lr]=kv.z*cc; Ks[(col+3)*64+lr]=kv.w*cc;
            float4 vv = *(const float4*)(g_V + base + (size_t)(j0 + lr)*DD + col);
            *(float4*)(Vs + lr*64 + col) = vv;
        }
        __syncthreads();

        float s[4][4] = {};
        #pragma unroll
        for (int d = 0; d < 64; d++) {
            float a[4], b[4];
            #pragma unroll
            for (int i = 0; i < 4; i++) a[i] = Qs[d*64 + tr*4 + i];
            #pragma unroll
            for (int j = 0; j < 4; j++) b[j] = Ks[d*64 + tc*4 + j];
            #pragma unroll
            for (int i = 0; i < 4; i++)
                #pragma unroll
                for (int j = 0; j < 4; j++)
                    s[i][j] = fmaf(a[i], b[j], s[i][j]);
        }

        if (!diag) {
            #pragma unroll
            for (int i = 0; i < 4; i++) {
                float rc = exp2f((float)(tr*4 + i + dist - 63) * lg);
                #pragma unroll
                for (int j = 0; j < 4; j++) s[i][j] *= rc;
            }
        } else {
            #pragma unroll
            for (int i = 0; i < 4; i++) {
                int ri = tr*4 + i;
                #pragma unroll
                for (int j = 0; j < 4; j++) {
                    int rj = tc*4 + j;
                    s[i][j] = (ri >= rj) ? s[i][j] * exp2f((float)(ri - rj) * lg) : 0.0f;
                }
            }
        }

        #pragma unroll
        for (int j = 0; j < 4; j++)
            #pragma unroll
            for (int i = 0; i < 4; i++)
                Ss[(tc*4 + j)*65 + tr*4 + i] = s[i][j];
        __syncthreads();

        #pragma unroll
        for (int jj = 0; jj < 64; jj++) {
            float a[4], b[4];
            #pragma unroll
            for (int i = 0; i < 4; i++) a[i] = Ss[jj*65 + tr*4 + i];
            #pragma unroll
            for (int c = 0; c < 4; c++) b[c] = Vs[jj*64 + tc*4 + c];
            #pragma unroll
            for (int i = 0; i < 4; i++)
                #pragma unroll
                for (int c = 0; c < 4; c++)
                    acc[i][c] = fmaf(a[i], b[c], acc[i][c]);
        }
        __syncthreads();
    }

    float lsum = 0.0f, lsq = 0.0f;
    #pragma unroll
    for (int i = 0; i < 4; i++) {
        float4 v4;
        float* pv = (float*)&v4;
        #pragma unroll
        for (int c = 0; c < 4; c++) {
            float v = acc[i][c];
            pv[c] = v; lsum += v; lsq += v*v;
        }
        *(float4*)(g_Y + base + (size_t)(i0 + tr*4 + i)*DD + tc*4) = v4;
    }

    #pragma unroll
    for (int o = 16; o > 0; o >>= 1) {
        lsum += __shfl_down_sync(0xffffffffu, lsum, o);
        lsq  += __shfl_down_sync(0xffffffffu, lsq,  o);
    }
    int wid = tid >> 5, lane = tid & 31;
    if (lane == 0) { Ss[wid] = lsum; Ss[8 + wid] = lsq; }
    __syncthreads();
    if (tid == 0) {
        float s0 = 0.0f, s1 = 0.0f;
        #pragma unroll
        for (int w = 0; w < 8; w++) { s0 += Ss[w]; s1 += Ss[8 + w]; }
        g_part[(bh*QTILES + qt)*2 + 0] = s0;
        g_part[(bh*QTILES + qt)*2 + 1] = s1;
    }
}

__global__ void norm_stats_kernel() {
    int i = threadIdx.x;
    if (i < BB*HH) {
        float s = 0.0f, q = 0.0f;
        for (int t = 0; t < QTILES; t++) {
            s += g_part[(i*QTILES + t)*2 + 0];
            q += g_part[(i*QTILES + t)*2 + 1];
        }
        float n = (float)(TT * DD);
        float mu = s / n;
        float var = q / n - mu * mu;
        g_norm[i*2 + 0] = mu;
        g_norm[i*2 + 1] = rsqrtf(var + 1e-5f);
    }
}

// Apply GroupNorm -> g_Yn[m][k]  (m = b*T+t, k = h*64+d)
__global__ void yn_kernel(const float* __restrict__ gnw, const float* __restrict__ gnb) {
    int m = blockIdx.x;
    int k = threadIdx.x * 4;
    int b = m >> 11, t = m & (TT - 1);
    int h = k >> 6, d = k & 63;
    int bh = b*HH + h;
    float mu = g_norm[bh*2 + 0], ri = g_norm[bh*2 + 1];
    float4 y = *(const float4*)(g_Y + ((size_t)bh*TT + t)*DD + d);
    float4 w = *(const float4*)(gnw + k);
    float4 gb = *(const float4*)(gnb + k);
    float4 o;
    o.x = (y.x - mu)*ri*w.x + gb.x;
    o.y = (y.y - mu)*ri*w.y + gb.y;
    o.z = (y.z - mu)*ri*w.z + gb.z;
    o.w = (y.w - mu)*ri*w.w + gb.w;
    *(float4*)(g_Yn + (size_t)m*CC + k) = o;
}

// ---------------------------------------------------------------------------
extern "C" void kernel_launch(void* const* d_in, const int* in_sizes, int n_in,
                              void* d_out, int out_size) {
    const float* x   = (const float*)d_in[0];
    const float* Wq  = (const float*)d_in[1];
    const float* Wk  = (const float*)d_in[2];
    const float* Wv  = (const float*)d_in[3];
    const float* Wo  = (const float*)d_in[4];
    const float* gnw = (const float*)d_in[5];
    const float* gnb = (const float*)d_in[6];
    float* out = (float*)d_out;

    const int RET_SMEM = (12288 + 64*65) * 4;  // 65792 B
    cudaFuncSetAttribute(retention_kernel,
                         cudaFuncAttributeMaxDynamicSharedMemorySize, RET_SMEM);
    cudaFuncSetAttribute(gemm_kernel,
                         cudaFuncAttributeMaxDynamicSharedMemorySize, GEMM_SMEM);

    dim3 gg(MM/128, CC/128);  // 32 x 8
    gemm_kernel<<<gg, 256, GEMM_SMEM>>>(x, Wq, nullptr, 0, 0.125f);
    gemm_kernel<<<gg, 256, GEMM_SMEM>>>(x, Wk, nullptr, 1, 1.0f);
    gemm_kernel<<<gg, 256, GEMM_SMEM>>>(x, Wv, nullptr, 2, 1.0f);

    dim3 gr(QTILES, BB*HH);
    retention_kernel<<<gr, 256, RET_SMEM>>>();

    norm_stats_kernel<<<1, 32>>>();
    yn_kernel<<<MM, 256>>>(gnw, gnb);

    gemm_kernel<<<gg, 256, GEMM_SMEM>>>(nullptr, Wo, out, 3, 1.0f);
}

// round 9
// speedup vs baseline: 2.2842x; 2.2842x over previous
#include <cuda_runtime.h>
#include <cuda_bf16.h>
#include <math.h>
#include <stdint.h>

#define BB 2
#define TT 2048
#define CC 1024
#define HH 16
#define DD 64
#define MM (BB*TT)      // 4096
#define QT2 16          // 128-row query tiles

// Scratch (device globals: allocation-free, graph-capture safe)
__device__ float g_V[BB*HH*TT*DD];
__device__ float g_Y[BB*HH*TT*DD];
__device__ float g_Yn[MM*CC];
__device__ __nv_bfloat16 g_Qh[BB*HH*TT*DD], g_Ql[BB*HH*TT*DD];
__device__ __nv_bfloat16 g_Kh[BB*HH*TT*DD], g_Kl[BB*HH*TT*DD];
__device__ __nv_bfloat16 g_Vth[BB*HH*DD*TT], g_Vtl[BB*HH*DD*TT];  // [bh][d][t]
__device__ float g_part[BB*HH*QT2*2];
__device__ float g_norm[BB*HH*2];

// ===========================================================================
// mma.sync bf16 (baseline ISA — sm_103-safe; validated in R8, rel_err 9.6e-6)
// ===========================================================================
__device__ __forceinline__ void mma16816(float d[4], const uint32_t a[4],
                                         const uint32_t b[2]) {
    asm volatile(
        "mma.sync.aligned.m16n8k16.row.col.f32.bf16.bf16.f32 "
        "{%0,%1,%2,%3}, {%4,%5,%6,%7}, {%8,%9}, {%0,%1,%2,%3};"
        : "+f"(d[0]), "+f"(d[1]), "+f"(d[2]), "+f"(d[3])
        : "r"(a[0]), "r"(a[1]), "r"(a[2]), "r"(a[3]), "r"(b[0]), "r"(b[1]));
}

__device__ __forceinline__ void cvt_pair(float a, float b, uint32_t& hi, uint32_t& lo) {
    __nv_bfloat162 h, l;
    h.x = __float2bfloat16(a); h.y = __float2bfloat16(b);
    l.x = __float2bfloat16(a - __bfloat162float(h.x));
    l.y = __float2bfloat16(b - __bfloat162float(h.y));
    hi = *(uint32_t*)&h; lo = *(uint32_t*)&l;
}

// ===========================================================================
// Split-bf16 GEMM: D[m,n] = sum_k A[m,k] * W[n,k]. CTA 128x128, Kch 64,
// 256 thr, warps 4x2, warp tile 32x64.
// mode 0: Q -> g_Qh/g_Ql (scaled);  mode 1: K -> g_Kh/g_Kl;
// mode 2: V -> g_V (f32, BHTD);     mode 3: g_Yn @ Wo.T -> OutDirect.
// ===========================================================================
#define KCH 64
#define STR 72
#define TILE_U (128*STR)
#define GEMM_SMEM (4*TILE_U*2)           // 73728 B

__global__ void __launch_bounds__(256, 1)
gemm_kernel(const float* __restrict__ A, const float* __restrict__ W,
            float* __restrict__ OutDirect, int mode, float scale) {
    extern __shared__ __nv_bfloat16 smB[];
    __nv_bfloat16* Ahi = smB;
    __nv_bfloat16* Alo = smB + TILE_U;
    __nv_bfloat16* Bhi = smB + 2*TILE_U;
    __nv_bfloat16* Blo = smB + 3*TILE_U;

    int tid = threadIdx.x;
    int wid = tid >> 5, lane = tid & 31;
    int g = lane >> 2, tg = lane & 3;
    int wm = wid >> 1, wn = wid & 1;
    int m0 = blockIdx.x * 128, n0 = blockIdx.y * 128;

    const float* Ap = A ? A : g_Yn;
    int lrow = tid >> 1, lhalf = (tid & 1) * 32;
    const float* Arow = Ap + (size_t)(m0 + lrow) * CC + lhalf;
    const float* Brow = W  + (size_t)(n0 + lrow) * CC + lhalf;

    float acc[2][8][4] = {};

    for (int k0 = 0; k0 < CC; k0 += KCH) {
        #pragma unroll
        for (int j = 0; j < 8; j++) {
            float4 a = *(const float4*)(Arow + k0 + j*4);
            uint32_t h0, l0, h1, l1;
            cvt_pair(a.x, a.y, h0, l0); cvt_pair(a.z, a.w, h1, l1);
            int u = lrow*STR + lhalf + j*4;
            *(uint2*)(Ahi + u) = make_uint2(h0, h1);
            *(uint2*)(Alo + u) = make_uint2(l0, l1);

            float4 b = *(const float4*)(Brow + k0 + j*4);
            cvt_pair(b.x, b.y, h0, l0); cvt_pair(b.z, b.w, h1, l1);
            *(uint2*)(Bhi + u) = make_uint2(h0, h1);
            *(uint2*)(Blo + u) = make_uint2(l0, l1);
        }
        __syncthreads();

        #pragma unroll
        for (int ks = 0; ks < 4; ks++) {
            int kc = ks*16 + tg*2;
            uint32_t ah[2][4], al[2][4];
            #pragma unroll
            for (int mf = 0; mf < 2; mf++) {
                int r = wm*32 + mf*16 + g;
                ah[mf][0] = *(const uint32_t*)(Ahi + (r  )*STR + kc);
                ah[mf][1] = *(const uint32_t*)(Ahi + (r+8)*STR + kc);
                ah[mf][2] = *(const uint32_t*)(Ahi + (r  )*STR + kc + 8);
                ah[mf][3] = *(const uint32_t*)(Ahi + (r+8)*STR + kc + 8);
                al[mf][0] = *(const uint32_t*)(Alo + (r  )*STR + kc);
                al[mf][1] = *(const uint32_t*)(Alo + (r+8)*STR + kc);
                al[mf][2] = *(const uint32_t*)(Alo + (r  )*STR + kc + 8);
                al[mf][3] = *(const uint32_t*)(Alo + (r+8)*STR + kc + 8);
            }
            #pragma unroll
            for (int nf = 0; nf < 8; nf++) {
                int n = wn*64 + nf*8 + g;
                uint32_t bh[2], bl[2];
                bh[0] = *(const uint32_t*)(Bhi + n*STR + kc);
                bh[1] = *(const uint32_t*)(Bhi + n*STR + kc + 8);
                bl[0] = *(const uint32_t*)(Blo + n*STR + kc);
                bl[1] = *(const uint32_t*)(Blo + n*STR + kc + 8);
                #pragma unroll
                for (int mf = 0; mf < 2; mf++) {
                    mma16816(acc[mf][nf], ah[mf], bh);
                    mma16816(acc[mf][nf], ah[mf], bl);
                    mma16816(acc[mf][nf], al[mf], bh);
                }
            }
        }
        __syncthreads();
    }

    if (mode == 3) {
        #pragma unroll
        for (int mf = 0; mf < 2; mf++) {
            int m = m0 + wm*32 + mf*16 + g;
            #pragma unroll
            for (int nf = 0; nf < 8; nf++) {
                int n = n0 + wn*64 + nf*8 + tg*2;
                float* d = acc[mf][nf];
                *(float2*)(OutDirect + (size_t)m*CC + n)     = make_float2(d[0], d[1]);
                *(float2*)(OutDirect + (size_t)(m+8)*CC + n) = make_float2(d[2], d[3]);
            }
        }
    } else if (mode == 2) {
        #pragma unroll
        for (int mf = 0; mf < 2; mf++) {
            int m = m0 + wm*32 + mf*16 + g;
            int b = m >> 11, t = m & (TT - 1);
            #pragma unroll
            for (int nf = 0; nf < 8; nf++) {
                int n = n0 + wn*64 + nf*8 + tg*2;
                int h = n >> 6, d0 = n & 63;
                float* d = acc[mf][nf];
                size_t base = ((size_t)(b*HH + h)*TT);
                *(float2*)(g_V + (base + t  )*DD + d0) = make_float2(d[0], d[1]);
                *(float2*)(g_V + (base + t+8)*DD + d0) = make_float2(d[2], d[3]);
            }
        }
    } else {
        __nv_bfloat16* Oh = (mode == 0) ? g_Qh : g_Kh;
        __nv_bfloat16* Ol = (mode == 0) ? g_Ql : g_Kl;
        #pragma unroll
        for (int mf = 0; mf < 2; mf++) {
            int m = m0 + wm*32 + mf*16 + g;
            int b = m >> 11, t = m & (TT - 1);
            #pragma unroll
            for (int nf = 0; nf < 8; nf++) {
                int n = n0 + wn*64 + nf*8 + tg*2;
                int h = n >> 6, d0 = n & 63;
                float* d = acc[mf][nf];
                size_t base = ((size_t)(b*HH + h)*TT);
                uint32_t h0, l0, h1, l1;
                cvt_pair(d[0]*scale, d[1]*scale, h0, l0);
                cvt_pair(d[2]*scale, d[3]*scale, h1, l1);
                *(uint32_t*)(Oh + (base + t  )*DD + d0) = h0;
                *(uint32_t*)(Ol + (base + t  )*DD + d0) = l0;
                *(uint32_t*)(Oh + (base + t+8)*DD + d0) = h1;
                *(uint32_t*)(Ol + (base + t+8)*DD + d0) = l1;
            }
        }
    }
}

// ===========================================================================
// V transpose + split: g_V [bh][t][d] f32 -> g_Vth/g_Vtl [bh][d][t] bf16
// ===========================================================================
__global__ void vt_kernel() {
    __shared__ float ts[64][65];
    int bh = blockIdx.y, t0 = blockIdx.x * 64;
    size_t base = (size_t)bh * TT * DD;
    int tid = threadIdx.x;
    int r = tid >> 2, c = (tid & 3) * 16;

    #pragma unroll
    for (int i = 0; i < 4; i++) {
        float4 v = *(const float4*)(g_V + base + (size_t)(t0 + r)*DD + c + i*4);
        ts[r][c + i*4 + 0] = v.x; ts[r][c + i*4 + 1] = v.y;
        ts[r][c + i*4 + 2] = v.z; ts[r][c + i*4 + 3] = v.w;
    }
    __syncthreads();

    uint32_t hh[8], ll[8];
    #pragma unroll
    for (int p = 0; p < 8; p++)
        cvt_pair(ts[c + 2*p][r], ts[c + 2*p + 1][r], hh[p], ll[p]);
    size_t o = base + (size_t)r*TT + t0 + c;
    *(uint4*)(g_Vth + o)     = make_uint4(hh[0], hh[1], hh[2], hh[3]);
    *(uint4*)(g_Vth + o + 8) = make_uint4(hh[4], hh[5], hh[6], hh[7]);
    *(uint4*)(g_Vtl + o)     = make_uint4(ll[0], ll[1], ll[2], ll[3]);
    *(uint4*)(g_Vtl + o + 8) = make_uint4(ll[4], ll[5], ll[6], ll[7]);
}

// ===========================================================================
// Retention, tensor-core version. CTA = (bh, 128-row q tile); 8 warps along M
// (16 rows each, full kv width). kv tiles of 64. S acc frags convert in-reg
// to A frags for S@V. Decay rank-1 factorized; elementwise only on the
// diagonal band.
// ===========================================================================
#define RSTR 72
#define RET_SMEM ((128*RSTR*2 + 64*RSTR*4) * 2)   // 73728 B

__global__ void __launch_bounds__(256, 1) retention_kernel() {
    extern __shared__ __nv_bfloat16 sb[];
    __nv_bfloat16* SQh = sb;
    __nv_bfloat16* SQl = sb + 128*RSTR;
    __nv_bfloat16* SKh = sb + 256*RSTR;
    __nv_bfloat16* SKl = sb + 320*RSTR;
    __nv_bfloat16* SVh = sb + 384*RSTR;
    __nv_bfloat16* SVl = sb + 448*RSTR;
    __shared__ float red[16];

    int tid = threadIdx.x;
    int w = tid >> 5, lane = tid & 31, g = lane >> 2, tg = lane & 3;
    int qt = (QT2 - 1) - blockIdx.x;           // heavy tiles first
    int bh = blockIdx.y;
    int h = bh & (HH - 1);
    int i0 = qt * 128;
    size_t base = (size_t)bh * TT * DD;        // also [bh][d][t] base (same size)

    float lg = log2f(1.0f - exp2f(-5.0f - 0.5f * (float)h));

    // load Q tile (128 x 64) hi/lo
    {
        int r = tid >> 1, sq = (tid & 1) * 32;
        const __nv_bfloat16* qh = g_Qh + base + (size_t)(i0 + r)*DD + sq;
        const __nv_bfloat16* ql = g_Ql + base + (size_t)(i0 + r)*DD + sq;
        #pragma unroll
        for (int cch = 0; cch < 4; cch++) {
            *(uint4*)(SQh + r*RSTR + sq + cch*8) = *(const uint4*)(qh + cch*8);
            *(uint4*)(SQl + r*RSTR + sq + cch*8) = *(const uint4*)(ql + cch*8);
        }
    }

    // constant decay factors
    float rowA = exp2f(lg * (float)(w*16 + g));
    float rowB = rowA * exp2f(lg * 8.0f);
    float cstep = exp2f(-lg);
    float cf[8][2];
    #pragma unroll
    for (int nf = 0; nf < 8; nf++) {
        cf[nf][0] = exp2f(-lg * (float)(nf*8 + tg*2));
        cf[nf][1] = cf[nf][0] * cstep;
    }

    float acc_o[8][4] = {};
    int r4 = tid >> 2, s4 = (tid & 3) * 16;
    int jend = i0 + 128;

    for (int j0 = 0; j0 < jend; j0 += 64) {
        __syncthreads();   // previous tile fully consumed before overwrite
        {
            const __nv_bfloat16* kh = g_Kh + base + (size_t)(j0 + r4)*DD + s4;
            const __nv_bfloat16* kl = g_Kl + base + (size_t)(j0 + r4)*DD + s4;
            const __nv_bfloat16* vh = g_Vth + base + (size_t)r4*TT + j0 + s4;
            const __nv_bfloat16* vl = g_Vtl + base + (size_t)r4*TT + j0 + s4;
            *(uint4*)(SKh + r4*RSTR + s4)     = *(const uint4*)(kh);
            *(uint4*)(SKh + r4*RSTR + s4 + 8) = *(const uint4*)(kh + 8);
            *(uint4*)(SKl + r4*RSTR + s4)     = *(const uint4*)(kl);
            *(uint4*)(SKl + r4*RSTR + s4 + 8) = *(const uint4*)(kl + 8);
            *(uint4*)(SVh + r4*RSTR + s4)     = *(const uint4*)(vh);
            *(uint4*)(SVh + r4*RSTR + s4 + 8) = *(const uint4*)(vh + 8);
            *(uint4*)(SVl + r4*RSTR + s4)     = *(const uint4*)(vl);
            *(uint4*)(SVl + r4*RSTR + s4 + 8) = *(const uint4*)(vl + 8);
        }
        __syncthreads();

        int iMin = i0 + w*16, iMax = iMin + 15, jMax = j0 + 63;
        if (iMax < j0) continue;   // warp fully above diagonal: contributes 0

        // ---- S = Q K^T ----
        float s[8][4] = {};
        #pragma unroll
        for (int ks = 0; ks < 4; ks++) {
            int kc = ks*16 + tg*2;
            int ra = (w*16 + g)*RSTR, rb = ra + 8*RSTR;
            uint32_t ah[4], al[4];
            ah[0] = *(const uint32_t*)(SQh + ra + kc);
            ah[1] = *(const uint32_t*)(SQh + rb + kc);
            ah[2] = *(const uint32_t*)(SQh + ra + kc + 8);
            ah[3] = *(const uint32_t*)(SQh + rb + kc + 8);
            al[0] = *(const uint32_t*)(SQl + ra + kc);
            al[1] = *(const uint32_t*)(SQl + rb + kc);
            al[2] = *(const uint32_t*)(SQl + ra + kc + 8);
            al[3] = *(const uint32_t*)(SQl + rb + kc + 8);
            #pragma unroll
            for (int nf = 0; nf < 8; nf++) {
                int n = (nf*8 + g)*RSTR;
                uint32_t bh2[2], bl2[2];
                bh2[0] = *(const uint32_t*)(SKh + n + kc);
                bh2[1] = *(const uint32_t*)(SKh + n + kc + 8);
                bl2[0] = *(const uint32_t*)(SKl + n + kc);
                bl2[1] = *(const uint32_t*)(SKl + n + kc + 8);
                mma16816(s[nf], ah, bh2);
                mma16816(s[nf], ah, bl2);
                mma16816(s[nf], al, bh2);
            }
        }

        // ---- decay / causal mask ----
        if (iMin >= jMax) {
            float tf = exp2f(lg * (float)(i0 - j0));
            float fA = rowA * tf, fB = rowB * tf;
            #pragma unroll
            for (int nf = 0; nf < 8; nf++) {
                s[nf][0] *= fA * cf[nf][0];
                s[nf][1] *= fA * cf[nf][1];
                s[nf][2] *= fB * cf[nf][0];
                s[nf][3] *= fB * cf[nf][1];
            }
        } else {
            int riA = iMin + g, riB = riA + 8;
            #pragma unroll
            for (int nf = 0; nf < 8; nf++) {
                int jg = j0 + nf*8 + tg*2;
                int d0 = riA - jg, d1 = d0 - 1, d2 = riB - jg, d3 = d2 - 1;
                s[nf][0] = (d0 >= 0) ? s[nf][0] * exp2f(lg * (float)d0) : 0.0f;
                s[nf][1] = (d1 >= 0) ? s[nf][1] * exp2f(lg * (float)d1) : 0.0f;
                s[nf][2] = (d2 >= 0) ? s[nf][2] * exp2f(lg * (float)d2) : 0.0f;
                s[nf][3] = (d3 >= 0) ? s[nf][3] * exp2f(lg * (float)d3) : 0.0f;
            }
        }

        // ---- O += S V  (S acc frags -> A frags in registers) ----
        #pragma unroll
        for (int ks = 0; ks < 4; ks++) {
            uint32_t sh[4], sl[4];
            cvt_pair(s[2*ks  ][0], s[2*ks  ][1], sh[0], sl[0]);
            cvt_pair(s[2*ks  ][2], s[2*ks  ][3], sh[1], sl[1]);
            cvt_pair(s[2*ks+1][0], s[2*ks+1][1], sh[2], sl[2]);
            cvt_pair(s[2*ks+1][2], s[2*ks+1][3], sh[3], sl[3]);
            int kc = ks*16 + tg*2;
            #pragma unroll
            for (int nd = 0; nd < 8; nd++) {
                int n = (nd*8 + g)*RSTR;
                uint32_t vh[2], vl[2];
                vh[0] = *(const uint32_t*)(SVh + n + kc);
                vh[1] = *(const uint32_t*)(SVh + n + kc + 8);
                vl[0] = *(const uint32_t*)(SVl + n + kc);
                vl[1] = *(const uint32_t*)(SVl + n + kc + 8);
                mma16816(acc_o[nd], sh, vh);
                mma16816(acc_o[nd], sh, vl);
                mma16816(acc_o[nd], sl, vh);
            }
        }
    }

    // ---- write y + GroupNorm partial stats ----
    float lsum = 0.0f, lsq = 0.0f;
    int riA = i0 + w*16 + g;
    #pragma unroll
    for (int nd = 0; nd < 8; nd++) {
        int d0 = nd*8 + tg*2;
        float* d = acc_o[nd];
        lsum += d[0] + d[1] + d[2] + d[3];
        lsq  += d[0]*d[0] + d[1]*d[1] + d[2]*d[2] + d[3]*d[3];
        *(float2*)(g_Y + base + (size_t)riA*DD + d0)     = make_float2(d[0], d[1]);
        *(float2*)(g_Y + base + (size_t)(riA+8)*DD + d0) = make_float2(d[2], d[3]);
    }
    #pragma unroll
    for (int o = 16; o > 0; o >>= 1) {
        lsum += __shfl_down_sync(0xffffffffu, lsum, o);
        lsq  += __shfl_down_sync(0xffffffffu, lsq,  o);
    }
    if (lane == 0) { red[w*2] = lsum; red[w*2 + 1] = lsq; }
    __syncthreads();
    if (tid == 0) {
        float s0 = 0.0f, s1 = 0.0f;
        #pragma unroll
        for (int x = 0; x < 8; x++) { s0 += red[x*2]; s1 += red[x*2 + 1]; }
        g_part[(bh*QT2 + qt)*2 + 0] = s0;
        g_part[(bh*QT2 + qt)*2 + 1] = s1;
    }
}

__global__ void norm_stats_kernel() {
    int i = threadIdx.x;
    if (i < BB*HH) {
        float s = 0.0f, q = 0.0f;
        for (int t = 0; t < QT2; t++) {
            s += g_part[(i*QT2 + t)*2 + 0];
            q += g_part[(i*QT2 + t)*2 + 1];
        }
        float n = (float)(TT * DD);
        float mu = s / n;
        float var = q / n - mu * mu;
        g_norm[i*2 + 0] = mu;
        g_norm[i*2 + 1] = rsqrtf(var + 1e-5f);
    }
}

// GroupNorm apply -> g_Yn[m][k]
__global__ void yn_kernel(const float* __restrict__ gnw, const float* __restrict__ gnb) {
    int m = blockIdx.x;
    int k = threadIdx.x * 4;
    int b = m >> 11, t = m & (TT - 1);
    int h = k >> 6, d = k & 63;
    int bh = b*HH + h;
    float mu = g_norm[bh*2 + 0], ri = g_norm[bh*2 + 1];
    float4 y = *(const float4*)(g_Y + ((size_t)bh*TT + t)*DD + d);
    float4 w = *(const float4*)(gnw + k);
    float4 gb = *(const float4*)(gnb + k);
    float4 o;
    o.x = (y.x - mu)*ri*w.x + gb.x;
    o.y = (y.y - mu)*ri*w.y + gb.y;
    o.z = (y.z - mu)*ri*w.z + gb.z;
    o.w = (y.w - mu)*ri*w.w + gb.w;
    *(float4*)(g_Yn + (size_t)m*CC + k) = o;
}

// ---------------------------------------------------------------------------
extern "C" void kernel_launch(void* const* d_in, const int* in_sizes, int n_in,
                              void* d_out, int out_size) {
    const float* x   = (const float*)d_in[0];
    const float* Wq  = (const float*)d_in[1];
    const float* Wk  = (const float*)d_in[2];
    const float* Wv  = (const float*)d_in[3];
    const float* Wo  = (const float*)d_in[4];
    const float* gnw = (const float*)d_in[5];
    const float* gnb = (const float*)d_in[6];
    float* out = (float*)d_out;

    cudaFuncSetAttribute(gemm_kernel,
                         cudaFuncAttributeMaxDynamicSharedMemorySize, GEMM_SMEM);
    cudaFuncSetAttribute(retention_kernel,
                         cudaFuncAttributeMaxDynamicSharedMemorySize, RET_SMEM);

    dim3 gg(MM/128, CC/128);  // 32 x 8
    gemm_kernel<<<gg, 256, GEMM_SMEM>>>(x, Wq, nullptr, 0, 0.125f);
    gemm_kernel<<<gg, 256, GEMM_SMEM>>>(x, Wk, nullptr, 1, 1.0f);
    gemm_kernel<<<gg, 256, GEMM_SMEM>>>(x, Wv, nullptr, 2, 1.0f);

    vt_kernel<<<dim3(TT/64, BB*HH), 256>>>();

    retention_kernel<<<dim3(QT2, BB*HH), 256, RET_SMEM>>>();

    norm_stats_kernel<<<1, 32>>>();
    yn_kernel<<<MM, 256>>>(gnw, gnb);

    gemm_kernel<<<gg, 256, GEMM_SMEM>>>(nullptr, Wo, out, 3, 1.0f);
}

// round 10
// speedup vs baseline: 2.5104x; 1.0990x over previous
#include <cuda_runtime.h>
#include <cuda_bf16.h>
#include <math.h>
#include <stdint.h>

#define BB 2
#define TT 2048
#define CC 1024
#define HH 16
#define DD 64
#define MM (BB*TT)      // 4096
#define QT2 16          // 128-row query tiles

// Scratch (device globals: allocation-free, graph-capture safe)
__device__ float g_V[BB*HH*TT*DD];
__device__ float g_Y[BB*HH*TT*DD];
__device__ float g_Yn[MM*CC];
__device__ __nv_bfloat16 g_Qh[BB*HH*TT*DD], g_Ql[BB*HH*TT*DD];
__device__ __nv_bfloat16 g_Kh[BB*HH*TT*DD], g_Kl[BB*HH*TT*DD];
__device__ __nv_bfloat16 g_Vth[BB*HH*DD*TT], g_Vtl[BB*HH*DD*TT];  // [bh][d][t]
__device__ float g_part[BB*HH*QT2*2];
__device__ float g_norm[BB*HH*2];

// ===========================================================================
// mma.sync bf16 (baseline ISA — sm_103-safe; validated R8/R9)
// ===========================================================================
__device__ __forceinline__ void mma16816(float d[4], const uint32_t a[4],
                                         const uint32_t b[2]) {
    asm volatile(
        "mma.sync.aligned.m16n8k16.row.col.f32.bf16.bf16.f32 "
        "{%0,%1,%2,%3}, {%4,%5,%6,%7}, {%8,%9}, {%0,%1,%2,%3};"
        : "+f"(d[0]), "+f"(d[1]), "+f"(d[2]), "+f"(d[3])
        : "r"(a[0]), "r"(a[1]), "r"(a[2]), "r"(a[3]), "r"(b[0]), "r"(b[1]));
}

__device__ __forceinline__ void cvt_pair(float a, float b, uint32_t& hi, uint32_t& lo) {
    __nv_bfloat162 h, l;
    h.x = __float2bfloat16(a); h.y = __float2bfloat16(b);
    l.x = __float2bfloat16(a - __bfloat162float(h.x));
    l.y = __float2bfloat16(b - __bfloat162float(h.y));
    hi = *(uint32_t*)&h; lo = *(uint32_t*)&l;
}

// ===========================================================================
// Split-bf16 GEMM: D[m,n] = sum_k A[m,k] * W[n,k]. CTA 128x128, Kch 64,
// 256 thr, warps 4x2, warp tile 32x64. Occupancy target: 2 CTAs/SM.
// mode 0: Q -> g_Qh/g_Ql (scaled);  mode 1: K -> g_Kh/g_Kl;
// mode 2: V -> g_V (f32, BHTD);     mode 3: g_Yn @ Wo.T -> OutDirect.
// ===========================================================================
#define KCH 64
#define STR 72
#define TILE_U (128*STR)
#define GEMM_SMEM (4*TILE_U*2)           // 73728 B  (2 CTAs = 147456 <= 228KB)

__global__ void __launch_bounds__(256, 2)
gemm_kernel(const float* __restrict__ A, const float* __restrict__ W,
            float* __restrict__ OutDirect, int mode, float scale) {
    extern __shared__ __nv_bfloat16 smB[];
    __nv_bfloat16* Ahi = smB;
    __nv_bfloat16* Alo = smB + TILE_U;
    __nv_bfloat16* Bhi = smB + 2*TILE_U;
    __nv_bfloat16* Blo = smB + 3*TILE_U;

    int tid = threadIdx.x;
    int wid = tid >> 5, lane = tid & 31;
    int g = lane >> 2, tg = lane & 3;
    int wm = wid >> 1, wn = wid & 1;
    int m0 = blockIdx.x * 128, n0 = blockIdx.y * 128;

    const float* Ap = A ? A : g_Yn;
    int lrow = tid >> 1, lhalf = (tid & 1) * 32;
    const float* Arow = Ap + (size_t)(m0 + lrow) * CC + lhalf;
    const float* Brow = W  + (size_t)(n0 + lrow) * CC + lhalf;

    float acc[2][8][4] = {};

    for (int k0 = 0; k0 < CC; k0 += KCH) {
        #pragma unroll
        for (int j = 0; j < 8; j++) {
            float4 a = *(const float4*)(Arow + k0 + j*4);
            uint32_t h0, l0, h1, l1;
            cvt_pair(a.x, a.y, h0, l0); cvt_pair(a.z, a.w, h1, l1);
            int u = lrow*STR + lhalf + j*4;
            *(uint2*)(Ahi + u) = make_uint2(h0, h1);
            *(uint2*)(Alo + u) = make_uint2(l0, l1);

            float4 b = *(const float4*)(Brow + k0 + j*4);
            cvt_pair(b.x, b.y, h0, l0); cvt_pair(b.z, b.w, h1, l1);
            *(uint2*)(Bhi + u) = make_uint2(h0, h1);
            *(uint2*)(Blo + u) = make_uint2(l0, l1);
        }
        __syncthreads();

        #pragma unroll
        for (int ks = 0; ks < 4; ks++) {
            int kc = ks*16 + tg*2;
            uint32_t ah[2][4], al[2][4];
            #pragma unroll
            for (int mf = 0; mf < 2; mf++) {
                int r = wm*32 + mf*16 + g;
                ah[mf][0] = *(const uint32_t*)(Ahi + (r  )*STR + kc);
                ah[mf][1] = *(const uint32_t*)(Ahi + (r+8)*STR + kc);
                ah[mf][2] = *(const uint32_t*)(Ahi + (r  )*STR + kc + 8);
                ah[mf][3] = *(const uint32_t*)(Ahi + (r+8)*STR + kc + 8);
                al[mf][0] = *(const uint32_t*)(Alo + (r  )*STR + kc);
                al[mf][1] = *(const uint32_t*)(Alo + (r+8)*STR + kc);
                al[mf][2] = *(const uint32_t*)(Alo + (r  )*STR + kc + 8);
                al[mf][3] = *(const uint32_t*)(Alo + (r+8)*STR + kc + 8);
            }
            #pragma unroll
            for (int nf = 0; nf < 8; nf++) {
                int n = wn*64 + nf*8 + g;
                uint32_t bh[2], bl[2];
                bh[0] = *(const uint32_t*)(Bhi + n*STR + kc);
                bh[1] = *(const uint32_t*)(Bhi + n*STR + kc + 8);
                bl[0] = *(const uint32_t*)(Blo + n*STR + kc);
                bl[1] = *(const uint32_t*)(Blo + n*STR + kc + 8);
                #pragma unroll
                for (int mf = 0; mf < 2; mf++) {
                    mma16816(acc[mf][nf], ah[mf], bh);
                    mma16816(acc[mf][nf], ah[mf], bl);
                    mma16816(acc[mf][nf], al[mf], bh);
                }
            }
        }
        __syncthreads();
    }

    if (mode == 3) {
        #pragma unroll
        for (int mf = 0; mf < 2; mf++) {
            int m = m0 + wm*32 + mf*16 + g;
            #pragma unroll
            for (int nf = 0; nf < 8; nf++) {
                int n = n0 + wn*64 + nf*8 + tg*2;
                float* d = acc[mf][nf];
                *(float2*)(OutDirect + (size_t)m*CC + n)     = make_float2(d[0], d[1]);
                *(float2*)(OutDirect + (size_t)(m+8)*CC + n) = make_float2(d[2], d[3]);
            }
        }
    } else if (mode == 2) {
        #pragma unroll
        for (int mf = 0; mf < 2; mf++) {
            int m = m0 + wm*32 + mf*16 + g;
            int b = m >> 11, t = m & (TT - 1);
            #pragma unroll
            for (int nf = 0; nf < 8; nf++) {
                int n = n0 + wn*64 + nf*8 + tg*2;
                int h = n >> 6, d0 = n & 63;
                float* d = acc[mf][nf];
                size_t base = ((size_t)(b*HH + h)*TT);
                *(float2*)(g_V + (base + t  )*DD + d0) = make_float2(d[0], d[1]);
                *(float2*)(g_V + (base + t+8)*DD + d0) = make_float2(d[2], d[3]);
            }
        }
    } else {
        __nv_bfloat16* Oh = (mode == 0) ? g_Qh : g_Kh;
        __nv_bfloat16* Ol = (mode == 0) ? g_Ql : g_Kl;
        #pragma unroll
        for (int mf = 0; mf < 2; mf++) {
            int m = m0 + wm*32 + mf*16 + g;
            int b = m >> 11, t = m & (TT - 1);
            #pragma unroll
            for (int nf = 0; nf < 8; nf++) {
                int n = n0 + wn*64 + nf*8 + tg*2;
                int h = n >> 6, d0 = n & 63;
                float* d = acc[mf][nf];
                size_t base = ((size_t)(b*HH + h)*TT);
                uint32_t h0, l0, h1, l1;
                cvt_pair(d[0]*scale, d[1]*scale, h0, l0);
                cvt_pair(d[2]*scale, d[3]*scale, h1, l1);
                *(uint32_t*)(Oh + (base + t  )*DD + d0) = h0;
                *(uint32_t*)(Ol + (base + t  )*DD + d0) = l0;
                *(uint32_t*)(Oh + (base + t+8)*DD + d0) = h1;
                *(uint32_t*)(Ol + (base + t+8)*DD + d0) = l1;
            }
        }
    }
}

// ===========================================================================
// V transpose + split: g_V [bh][t][d] f32 -> g_Vth/g_Vtl [bh][d][t] bf16
// ===========================================================================
__global__ void vt_kernel() {
    __shared__ float ts[64][65];
    int bh = blockIdx.y, t0 = blockIdx.x * 64;
    size_t base = (size_t)bh * TT * DD;
    int tid = threadIdx.x;
    int r = tid >> 2, c = (tid & 3) * 16;

    #pragma unroll
    for (int i = 0; i < 4; i++) {
        float4 v = *(const float4*)(g_V + base + (size_t)(t0 + r)*DD + c + i*4);
        ts[r][c + i*4 + 0] = v.x; ts[r][c + i*4 + 1] = v.y;
        ts[r][c + i*4 + 2] = v.z; ts[r][c + i*4 + 3] = v.w;
    }
    __syncthreads();

    uint32_t hh[8], ll[8];
    #pragma unroll
    for (int p = 0; p < 8; p++)
        cvt_pair(ts[c + 2*p][r], ts[c + 2*p + 1][r], hh[p], ll[p]);
    size_t o = base + (size_t)r*TT + t0 + c;
    *(uint4*)(g_Vth + o)     = make_uint4(hh[0], hh[1], hh[2], hh[3]);
    *(uint4*)(g_Vth + o + 8) = make_uint4(hh[4], hh[5], hh[6], hh[7]);
    *(uint4*)(g_Vtl + o)     = make_uint4(ll[0], ll[1], ll[2], ll[3]);
    *(uint4*)(g_Vtl + o + 8) = make_uint4(ll[4], ll[5], ll[6], ll[7]);
}

// ===========================================================================
// Retention, tensor-core version (R9 structure). Occupancy target 2 CTAs/SM.
// CTA = (bh, 128-row q tile); 8 warps along M; kv tiles 64; S frags
// convert in-register for S@V; decay rank-1 off-diagonal.
// ===========================================================================
#define RSTR 72
#define RET_SMEM ((128*RSTR*2 + 64*RSTR*4) * 2)   // 73728 B

__global__ void __launch_bounds__(256, 2) retention_kernel() {
    extern __shared__ __nv_bfloat16 sb[];
    __nv_bfloat16* SQh = sb;
    __nv_bfloat16* SQl = sb + 128*RSTR;
    __nv_bfloat16* SKh = sb + 256*RSTR;
    __nv_bfloat16* SKl = sb + 320*RSTR;
    __nv_bfloat16* SVh = sb + 384*RSTR;
    __nv_bfloat16* SVl = sb + 448*RSTR;
    __shared__ float red[16];

    int tid = threadIdx.x;
    int w = tid >> 5, lane = tid & 31, g = lane >> 2, tg = lane & 3;
    int qt = (QT2 - 1) - blockIdx.x;           // heavy tiles first
    int bh = blockIdx.y;
    int h = bh & (HH - 1);
    int i0 = qt * 128;
    size_t base = (size_t)bh * TT * DD;

    float lg = log2f(1.0f - exp2f(-5.0f - 0.5f * (float)h));

    // load Q tile (128 x 64) hi/lo
    {
        int r = tid >> 1, sq = (tid & 1) * 32;
        const __nv_bfloat16* qh = g_Qh + base + (size_t)(i0 + r)*DD + sq;
        const __nv_bfloat16* ql = g_Ql + base + (size_t)(i0 + r)*DD + sq;
        #pragma unroll
        for (int cch = 0; cch < 4; cch++) {
            *(uint4*)(SQh + r*RSTR + sq + cch*8) = *(const uint4*)(qh + cch*8);
            *(uint4*)(SQl + r*RSTR + sq + cch*8) = *(const uint4*)(ql + cch*8);
        }
    }

    // constant decay factors (reg-lean: 8 col factors + step)
    float rowA = exp2f(lg * (float)(w*16 + g));
    float rowB = rowA * exp2f(lg * 8.0f);
    float cstep = exp2f(-lg);
    float cf0[8];
    #pragma unroll
    for (int nf = 0; nf < 8; nf++)
        cf0[nf] = exp2f(-lg * (float)(nf*8 + tg*2));

    float acc_o[8][4] = {};
    int r4 = tid >> 2, s4 = (tid & 3) * 16;
    int jend = i0 + 128;

    for (int j0 = 0; j0 < jend; j0 += 64) {
        __syncthreads();   // previous tile fully consumed before overwrite
        {
            const __nv_bfloat16* kh = g_Kh + base + (size_t)(j0 + r4)*DD + s4;
            const __nv_bfloat16* kl = g_Kl + base + (size_t)(j0 + r4)*DD + s4;
            const __nv_bfloat16* vh = g_Vth + base + (size_t)r4*TT + j0 + s4;
            const __nv_bfloat16* vl = g_Vtl + base + (size_t)r4*TT + j0 + s4;
            *(uint4*)(SKh + r4*RSTR + s4)     = *(const uint4*)(kh);
            *(uint4*)(SKh + r4*RSTR + s4 + 8) = *(const uint4*)(kh + 8);
            *(uint4*)(SKl + r4*RSTR + s4)     = *(const uint4*)(kl);
            *(uint4*)(SKl + r4*RSTR + s4 + 8) = *(const uint4*)(kl + 8);
            *(uint4*)(SVh + r4*RSTR + s4)     = *(const uint4*)(vh);
            *(uint4*)(SVh + r4*RSTR + s4 + 8) = *(const uint4*)(vh + 8);
            *(uint4*)(SVl + r4*RSTR + s4)     = *(const uint4*)(vl);
            *(uint4*)(SVl + r4*RSTR + s4 + 8) = *(const uint4*)(vl + 8);
        }
        __syncthreads();

        int iMin = i0 + w*16, iMax = iMin + 15, jMax = j0 + 63;
        if (iMax < j0) continue;   // warp fully above diagonal

        // ---- S = Q K^T ----
        float s[8][4] = {};
        #pragma unroll
        for (int ks = 0; ks < 4; ks++) {
            int kc = ks*16 + tg*2;
            int ra = (w*16 + g)*RSTR, rb = ra + 8*RSTR;
            uint32_t ah[4], al[4];
            ah[0] = *(const uint32_t*)(SQh + ra + kc);
            ah[1] = *(const uint32_t*)(SQh + rb + kc);
            ah[2] = *(const uint32_t*)(SQh + ra + kc + 8);
            ah[3] = *(const uint32_t*)(SQh + rb + kc + 8);
            al[0] = *(const uint32_t*)(SQl + ra + kc);
            al[1] = *(const uint32_t*)(SQl + rb + kc);
            al[2] = *(const uint32_t*)(SQl + ra + kc + 8);
            al[3] = *(const uint32_t*)(SQl + rb + kc + 8);
            #pragma unroll
            for (int nf = 0; nf < 8; nf++) {
                int n = (nf*8 + g)*RSTR;
                uint32_t bh2[2], bl2[2];
                bh2[0] = *(const uint32_t*)(SKh + n + kc);
                bh2[1] = *(const uint32_t*)(SKh + n + kc + 8);
                bl2[0] = *(const uint32_t*)(SKl + n + kc);
                bl2[1] = *(const uint32_t*)(SKl + n + kc + 8);
                mma16816(s[nf], ah, bh2);
                mma16816(s[nf], ah, bl2);
                mma16816(s[nf], al, bh2);
            }
        }

        // ---- decay / causal mask ----
        if (iMin >= jMax) {
            float tf = exp2f(lg * (float)(i0 - j0));
            float fA = rowA * tf, fB = rowB * tf;
            #pragma unroll
            for (int nf = 0; nf < 8; nf++) {
                float c0 = cf0[nf], c1 = c0 * cstep;
                s[nf][0] *= fA * c0;
                s[nf][1] *= fA * c1;
                s[nf][2] *= fB * c0;
                s[nf][3] *= fB * c1;
            }
        } else {
            int riA = iMin + g, riB = riA + 8;
            #pragma unroll
            for (int nf = 0; nf < 8; nf++) {
                int jg = j0 + nf*8 + tg*2;
                int d0 = riA - jg, d1 = d0 - 1, d2 = riB - jg, d3 = d2 - 1;
                s[nf][0] = (d0 >= 0) ? s[nf][0] * exp2f(lg * (float)d0) : 0.0f;
                s[nf][1] = (d1 >= 0) ? s[nf][1] * exp2f(lg * (float)d1) : 0.0f;
                s[nf][2] = (d2 >= 0) ? s[nf][2] * exp2f(lg * (float)d2) : 0.0f;
                s[nf][3] = (d3 >= 0) ? s[nf][3] * exp2f(lg * (float)d3) : 0.0f;
            }
        }

        // ---- O += S V  (S acc frags -> A frags in registers) ----
        #pragma unroll
        for (int ks = 0; ks < 4; ks++) {
            uint32_t sh[4], sl[4];
            cvt_pair(s[2*ks  ][0], s[2*ks  ][1], sh[0], sl[0]);
            cvt_pair(s[2*ks  ][2], s[2*ks  ][3], sh[1], sl[1]);
            cvt_pair(s[2*ks+1][0], s[2*ks+1][1], sh[2], sl[2]);
            cvt_pair(s[2*ks+1][2], s[2*ks+1][3], sh[3], sl[3]);
            int kc = ks*16 + tg*2;
            #pragma unroll
            for (int nd = 0; nd < 8; nd++) {
                int n = (nd*8 + g)*RSTR;
                uint32_t vh[2], vl[2];
                vh[0] = *(const uint32_t*)(SVh + n + kc);
                vh[1] = *(const uint32_t*)(SVh + n + kc + 8);
                vl[0] = *(const uint32_t*)(SVl + n + kc);
                vl[1] = *(const uint32_t*)(SVl + n + kc + 8);
                mma16816(acc_o[nd], sh, vh);
                mma16816(acc_o[nd], sh, vl);
                mma16816(acc_o[nd], sl, vh);
            }
        }
    }

    // ---- write y + GroupNorm partial stats ----
    float lsum = 0.0f, lsq = 0.0f;
    int riA = i0 + w*16 + g;
    #pragma unroll
    for (int nd = 0; nd < 8; nd++) {
        int d0 = nd*8 + tg*2;
        float* d = acc_o[nd];
        lsum += d[0] + d[1] + d[2] + d[3];
        lsq  += d[0]*d[0] + d[1]*d[1] + d[2]*d[2] + d[3]*d[3];
        *(float2*)(g_Y + base + (size_t)riA*DD + d0)     = make_float2(d[0], d[1]);
        *(float2*)(g_Y + base + (size_t)(riA+8)*DD + d0) = make_float2(d[2], d[3]);
    }
    #pragma unroll
    for (int o = 16; o > 0; o >>= 1) {
        lsum += __shfl_down_sync(0xffffffffu, lsum, o);
        lsq  += __shfl_down_sync(0xffffffffu, lsq,  o);
    }
    if (lane == 0) { red[w*2] = lsum; red[w*2 + 1] = lsq; }
    __syncthreads();
    if (tid == 0) {
        float s0 = 0.0f, s1 = 0.0f;
        #pragma unroll
        for (int x = 0; x < 8; x++) { s0 += red[x*2]; s1 += red[x*2 + 1]; }
        g_part[(bh*QT2 + qt)*2 + 0] = s0;
        g_part[(bh*QT2 + qt)*2 + 1] = s1;
    }
}

__global__ void norm_stats_kernel() {
    int i = threadIdx.x;
    if (i < BB*HH) {
        float s = 0.0f, q = 0.0f;
        for (int t = 0; t < QT2; t++) {
            s += g_part[(i*QT2 + t)*2 + 0];
            q += g_part[(i*QT2 + t)*2 + 1];
        }
        float n = (float)(TT * DD);
        float mu = s / n;
        float var = q / n - mu * mu;
        g_norm[i*2 + 0] = mu;
        g_norm[i*2 + 1] = rsqrtf(var + 1e-5f);
    }
}

// GroupNorm apply -> g_Yn[m][k]
__global__ void yn_kernel(const float* __restrict__ gnw, const float* __restrict__ gnb) {
    int m = blockIdx.x;
    int k = threadIdx.x * 4;
    int b = m >> 11, t = m & (TT - 1);
    int h = k >> 6, d = k & 63;
    int bh = b*HH + h;
    float mu = g_norm[bh*2 + 0], ri = g_norm[bh*2 + 1];
    float4 y = *(const float4*)(g_Y + ((size_t)bh*TT + t)*DD + d);
    float4 w = *(const float4*)(gnw + k);
    float4 gb = *(const float4*)(gnb + k);
    float4 o;
    o.x = (y.x - mu)*ri*w.x + gb.x;
    o.y = (y.y - mu)*ri*w.y + gb.y;
    o.z = (y.z - mu)*ri*w.z + gb.z;
    o.w = (y.w - mu)*ri*w.w + gb.w;
    *(float4*)(g_Yn + (size_t)m*CC + k) = o;
}

// ---------------------------------------------------------------------------
extern "C" void kernel_launch(void* const* d_in, const int* in_sizes, int n_in,
                              void* d_out, int out_size) {
    const float* x   = (const float*)d_in[0];
    const float* Wq  = (const float*)d_in[1];
    const float* Wk  = (const float*)d_in[2];
    const float* Wv  = (const float*)d_in[3];
    const float* Wo  = (const float*)d_in[4];
    const float* gnw = (const float*)d_in[5];
    const float* gnb = (const float*)d_in[6];
    float* out = (float*)d_out;

    cudaFuncSetAttribute(gemm_kernel,
                         cudaFuncAttributeMaxDynamicSharedMemorySize, GEMM_SMEM);
    cudaFuncSetAttribute(retention_kernel,
                         cudaFuncAttributeMaxDynamicSharedMemorySize, RET_SMEM);

    dim3 gg(MM/128, CC/128);  // 32 x 8
    gemm_kernel<<<gg, 256, GEMM_SMEM>>>(x, Wq, nullptr, 0, 0.125f);
    gemm_kernel<<<gg, 256, GEMM_SMEM>>>(x, Wk, nullptr, 1, 1.0f);
    gemm_kernel<<<gg, 256, GEMM_SMEM>>>(x, Wv, nullptr, 2, 1.0f);

    vt_kernel<<<dim3(TT/64, BB*HH), 256>>>();

    retention_kernel<<<dim3(QT2, BB*HH), 256, RET_SMEM>>>();

    norm_stats_kernel<<<1, 32>>>();
    yn_kernel<<<MM, 256>>>(gnw, gnb);

    gemm_kernel<<<gg, 256, GEMM_SMEM>>>(nullptr, Wo, out, 3, 1.0f);
}

// round 15
// speedup vs baseline: 2.9664x; 1.1817x over previous
#include <cuda_runtime.h>
#include <cuda_bf16.h>
#include <math.h>
#include <stdint.h>

#define BB 2
#define TT 2048
#define CC 1024
#define HH 16
#define DD 64
#define MM (BB*TT)      // 4096
#define QT2 16          // 128-row query tiles

// Scratch (device globals: allocation-free, graph-capture safe)
__device__ float g_V[BB*HH*TT*DD];
__device__ float g_Y[BB*HH*TT*DD];
__device__ __nv_bfloat16 g_Ah[MM*CC], g_Al[MM*CC];      // GEMM A operand (x, later norm(Y))
__device__ __nv_bfloat16 g_Wh[CC*CC], g_Wl[CC*CC];      // GEMM B operand (current W)
__device__ __nv_bfloat16 g_Qh[BB*HH*TT*DD], g_Ql[BB*HH*TT*DD];
__device__ __nv_bfloat16 g_Kh[BB*HH*TT*DD], g_Kl[BB*HH*TT*DD];
__device__ __nv_bfloat16 g_Vth[BB*HH*DD*TT], g_Vtl[BB*HH*DD*TT];  // [bh][d][t]
__device__ float g_part[BB*HH*QT2*2];
__device__ float g_norm[BB*HH*2];

// ===========================================================================
// mma.sync bf16 (baseline ISA — sm_103-safe; validated R8-R10)
// ===========================================================================
__device__ __forceinline__ void mma16816(float d[4], const uint32_t a[4],
                                         const uint32_t b[2]) {
    asm volatile(
        "mma.sync.aligned.m16n8k16.row.col.f32.bf16.bf16.f32 "
        "{%0,%1,%2,%3}, {%4,%5,%6,%7}, {%8,%9}, {%0,%1,%2,%3};"
        : "+f"(d[0]), "+f"(d[1]), "+f"(d[2]), "+f"(d[3])
        : "r"(a[0]), "r"(a[1]), "r"(a[2]), "r"(a[3]), "r"(b[0]), "r"(b[1]));
}

__device__ __forceinline__ void cvt_pair(float a, float b, uint32_t& hi, uint32_t& lo) {
    __nv_bfloat162 h, l;
    h.x = __float2bfloat16(a); h.y = __float2bfloat16(b);
    l.x = __float2bfloat16(a - __bfloat162float(h.x));
    l.y = __float2bfloat16(b - __bfloat162float(h.y));
    hi = *(uint32_t*)&h; lo = *(uint32_t*)&l;
}

// ===========================================================================
// Elementwise fp32 -> (bf16 hi, bf16 lo) split. Destination selected ON
// DEVICE (passing __device__ globals as host-side kernel args is UB — the
// R14 bug). which: 0 -> g_Ah/g_Al, 1 -> g_Wh/g_Wl.
// ===========================================================================
__global__ void split_kernel(const float* __restrict__ src, int which, int n4) {
    int i = blockIdx.x * blockDim.x + threadIdx.x;
    if (i < n4) {
        __nv_bfloat16* dh = which ? g_Wh : g_Ah;
        __nv_bfloat16* dl = which ? g_Wl : g_Al;
        float4 v = ((const float4*)src)[i];
        uint32_t h0, l0, h1, l1;
        cvt_pair(v.x, v.y, h0, l0); cvt_pair(v.z, v.w, h1, l1);
        ((uint2*)dh)[i] = make_uint2(h0, h1);
        ((uint2*)dl)[i] = make_uint2(l0, l1);
    }
}

// ===========================================================================
// Split-bf16 GEMM: D[m,n] = sum_k A[m,k] * W[n,k]; operands PRE-SPLIT
// (g_Ah/g_Al, g_Wh/g_Wl). CTA 128x128, Kch 64, 256 thr, warps 4x2,
// warp tile 32x64. Loader = raw bf16 uint4 copies (no convert).
// mode 0: Q -> g_Qh/g_Ql (scaled);  mode 1: K -> g_Kh/g_Kl;
// mode 2: V -> g_V (f32, BHTD);     mode 3: -> OutDirect [m][n].
// ===========================================================================
#define KCH 64
#define STR 72
#define TILE_U (128*STR)
#define GEMM_SMEM (4*TILE_U*2)           // 73728 B  (2 CTAs/SM fits)

__global__ void __launch_bounds__(256, 2)
gemm_kernel(float* __restrict__ OutDirect, int mode, float scale) {
    extern __shared__ __nv_bfloat16 smB[];
    __nv_bfloat16* Ahi = smB;
    __nv_bfloat16* Alo = smB + TILE_U;
    __nv_bfloat16* Bhi = smB + 2*TILE_U;
    __nv_bfloat16* Blo = smB + 3*TILE_U;

    int tid = threadIdx.x;
    int wid = tid >> 5, lane = tid & 31;
    int g = lane >> 2, tg = lane & 3;
    int wm = wid >> 1, wn = wid & 1;
    int m0 = blockIdx.x * 128, n0 = blockIdx.y * 128;

    int lrow = tid >> 1, lhalf = (tid & 1) * 32;
    const __nv_bfloat16* Ah = g_Ah + (size_t)(m0 + lrow) * CC + lhalf;
    const __nv_bfloat16* Al = g_Al + (size_t)(m0 + lrow) * CC + lhalf;
    const __nv_bfloat16* Bh = g_Wh + (size_t)(n0 + lrow) * CC + lhalf;
    const __nv_bfloat16* Bl = g_Wl + (size_t)(n0 + lrow) * CC + lhalf;

    float acc[2][8][4] = {};

    for (int k0 = 0; k0 < CC; k0 += KCH) {
        int u = lrow*STR + lhalf;
        #pragma unroll
        for (int j = 0; j < 4; j++) {
            *(uint4*)(Ahi + u + j*8) = *(const uint4*)(Ah + k0 + j*8);
            *(uint4*)(Alo + u + j*8) = *(const uint4*)(Al + k0 + j*8);
            *(uint4*)(Bhi + u + j*8) = *(const uint4*)(Bh + k0 + j*8);
            *(uint4*)(Blo + u + j*8) = *(const uint4*)(Bl + k0 + j*8);
        }
        __syncthreads();

        #pragma unroll
        for (int ks = 0; ks < 4; ks++) {
            int kc = ks*16 + tg*2;
            uint32_t ah[2][4], al[2][4];
            #pragma unroll
            for (int mf = 0; mf < 2; mf++) {
                int r = wm*32 + mf*16 + g;
                ah[mf][0] = *(const uint32_t*)(Ahi + (r  )*STR + kc);
                ah[mf][1] = *(const uint32_t*)(Ahi + (r+8)*STR + kc);
                ah[mf][2] = *(const uint32_t*)(Ahi + (r  )*STR + kc + 8);
                ah[mf][3] = *(const uint32_t*)(Ahi + (r+8)*STR + kc + 8);
                al[mf][0] = *(const uint32_t*)(Alo + (r  )*STR + kc);
                al[mf][1] = *(const uint32_t*)(Alo + (r+8)*STR + kc);
                al[mf][2] = *(const uint32_t*)(Alo + (r  )*STR + kc + 8);
                al[mf][3] = *(const uint32_t*)(Alo + (r+8)*STR + kc + 8);
            }
            #pragma unroll
            for (int nf = 0; nf < 8; nf++) {
                int n = wn*64 + nf*8 + g;
                uint32_t bh[2], bl[2];
                bh[0] = *(const uint32_t*)(Bhi + n*STR + kc);
                bh[1] = *(const uint32_t*)(Bhi + n*STR + kc + 8);
                bl[0] = *(const uint32_t*)(Blo + n*STR + kc);
                bl[1] = *(const uint32_t*)(Blo + n*STR + kc + 8);
                #pragma unroll
                for (int mf = 0; mf < 2; mf++) {
                    mma16816(acc[mf][nf], ah[mf], bh);
                    mma16816(acc[mf][nf], ah[mf], bl);
                    mma16816(acc[mf][nf], al[mf], bh);
                }
            }
        }
        __syncthreads();
    }

    if (mode == 3) {
        #pragma unroll
        for (int mf = 0; mf < 2; mf++) {
            int m = m0 + wm*32 + mf*16 + g;
            #pragma unroll
            for (int nf = 0; nf < 8; nf++) {
                int n = n0 + wn*64 + nf*8 + tg*2;
                float* d = acc[mf][nf];
                *(float2*)(OutDirect + (size_t)m*CC + n)     = make_float2(d[0], d[1]);
                *(float2*)(OutDirect + (size_t)(m+8)*CC + n) = make_float2(d[2], d[3]);
            }
        }
    } else if (mode == 2) {
        #pragma unroll
        for (int mf = 0; mf < 2; mf++) {
            int m = m0 + wm*32 + mf*16 + g;
            int b = m >> 11, t = m & (TT - 1);
            #pragma unroll
            for (int nf = 0; nf < 8; nf++) {
                int n = n0 + wn*64 + nf*8 + tg*2;
                int h = n >> 6, d0 = n & 63;
                float* d = acc[mf][nf];
                size_t base = ((size_t)(b*HH + h)*TT);
                *(float2*)(g_V + (base + t  )*DD + d0) = make_float2(d[0], d[1]);
                *(float2*)(g_V + (base + t+8)*DD + d0) = make_float2(d[2], d[3]);
            }
        }
    } else {
        __nv_bfloat16* Oh = (mode == 0) ? g_Qh : g_Kh;
        __nv_bfloat16* Ol = (mode == 0) ? g_Ql : g_Kl;
        #pragma unroll
        for (int mf = 0; mf < 2; mf++) {
            int m = m0 + wm*32 + mf*16 + g;
            int b = m >> 11, t = m & (TT - 1);
            #pragma unroll
            for (int nf = 0; nf < 8; nf++) {
                int n = n0 + wn*64 + nf*8 + tg*2;
                int h = n >> 6, d0 = n & 63;
                float* d = acc[mf][nf];
                size_t base = ((size_t)(b*HH + h)*TT);
                uint32_t h0, l0, h1, l1;
                cvt_pair(d[0]*scale, d[1]*scale, h0, l0);
                cvt_pair(d[2]*scale, d[3]*scale, h1, l1);
                *(uint32_t*)(Oh + (base + t  )*DD + d0) = h0;
                *(uint32_t*)(Ol + (base + t  )*DD + d0) = l0;
                *(uint32_t*)(Oh + (base + t+8)*DD + d0) = h1;
                *(uint32_t*)(Ol + (base + t+8)*DD + d0) = l1;
            }
        }
    }
}

// ===========================================================================
// V transpose + split: g_V [bh][t][d] f32 -> g_Vth/g_Vtl [bh][d][t] bf16
// ===========================================================================
__global__ void vt_kernel() {
    __shared__ float ts[64][65];
    int bh = blockIdx.y, t0 = blockIdx.x * 64;
    size_t base = (size_t)bh * TT * DD;
    int tid = threadIdx.x;
    int r = tid >> 2, c = (tid & 3) * 16;

    #pragma unroll
    for (int i = 0; i < 4; i++) {
        float4 v = *(const float4*)(g_V + base + (size_t)(t0 + r)*DD + c + i*4);
        ts[r][c + i*4 + 0] = v.x; ts[r][c + i*4 + 1] = v.y;
        ts[r][c + i*4 + 2] = v.z; ts[r][c + i*4 + 3] = v.w;
    }
    __syncthreads();

    uint32_t hh[8], ll[8];
    #pragma unroll
    for (int p = 0; p < 8; p++)
        cvt_pair(ts[c + 2*p][r], ts[c + 2*p + 1][r], hh[p], ll[p]);
    size_t o = base + (size_t)r*TT + t0 + c;
    *(uint4*)(g_Vth + o)     = make_uint4(hh[0], hh[1], hh[2], hh[3]);
    *(uint4*)(g_Vth + o + 8) = make_uint4(hh[4], hh[5], hh[6], hh[7]);
    *(uint4*)(g_Vtl + o)     = make_uint4(ll[0], ll[1], ll[2], ll[3]);
    *(uint4*)(g_Vtl + o + 8) = make_uint4(ll[4], ll[5], ll[6], ll[7]);
}

// ===========================================================================
// Retention, tensor-core version (unchanged from R10 passing kernel).
// ===========================================================================
#define RSTR 72
#define RET_SMEM ((128*RSTR*2 + 64*RSTR*4) * 2)   // 73728 B

__global__ void __launch_bounds__(256, 2) retention_kernel() {
    extern __shared__ __nv_bfloat16 sb[];
    __nv_bfloat16* SQh = sb;
    __nv_bfloat16* SQl = sb + 128*RSTR;
    __nv_bfloat16* SKh = sb + 256*RSTR;
    __nv_bfloat16* SKl = sb + 320*RSTR;
    __nv_bfloat16* SVh = sb + 384*RSTR;
    __nv_bfloat16* SVl = sb + 448*RSTR;
    __shared__ float red[16];

    int tid = threadIdx.x;
    int w = tid >> 5, lane = tid & 31, g = lane >> 2, tg = lane & 3;
    int qt = (QT2 - 1) - blockIdx.x;           // heavy tiles first
    int bh = blockIdx.y;
    int h = bh & (HH - 1);
    int i0 = qt * 128;
    size_t base = (size_t)bh * TT * DD;

    float lg = log2f(1.0f - exp2f(-5.0f - 0.5f * (float)h));

    // load Q tile (128 x 64) hi/lo
    {
        int r = tid >> 1, sq = (tid & 1) * 32;
        const __nv_bfloat16* qh = g_Qh + base + (size_t)(i0 + r)*DD + sq;
        const __nv_bfloat16* ql = g_Ql + base + (size_t)(i0 + r)*DD + sq;
        #pragma unroll
        for (int cch = 0; cch < 4; cch++) {
            *(uint4*)(SQh + r*RSTR + sq + cch*8) = *(const uint4*)(qh + cch*8);
            *(uint4*)(SQl + r*RSTR + sq + cch*8) = *(const uint4*)(ql + cch*8);
        }
    }

    // constant decay factors (reg-lean)
    float rowA = exp2f(lg * (float)(w*16 + g));
    float rowB = rowA * exp2f(lg * 8.0f);
    float cstep = exp2f(-lg);
    float cf0[8];
    #pragma unroll
    for (int nf = 0; nf < 8; nf++)
        cf0[nf] = exp2f(-lg * (float)(nf*8 + tg*2));

    float acc_o[8][4] = {};
    int r4 = tid >> 2, s4 = (tid & 3) * 16;
    int jend = i0 + 128;

    for (int j0 = 0; j0 < jend; j0 += 64) {
        __syncthreads();
        {
            const __nv_bfloat16* kh = g_Kh + base + (size_t)(j0 + r4)*DD + s4;
            const __nv_bfloat16* kl = g_Kl + base + (size_t)(j0 + r4)*DD + s4;
            const __nv_bfloat16* vh = g_Vth + base + (size_t)r4*TT + j0 + s4;
            const __nv_bfloat16* vl = g_Vtl + base + (size_t)r4*TT + j0 + s4;
            *(uint4*)(SKh + r4*RSTR + s4)     = *(const uint4*)(kh);
            *(uint4*)(SKh + r4*RSTR + s4 + 8) = *(const uint4*)(kh + 8);
            *(uint4*)(SKl + r4*RSTR + s4)     = *(const uint4*)(kl);
            *(uint4*)(SKl + r4*RSTR + s4 + 8) = *(const uint4*)(kl + 8);
            *(uint4*)(SVh + r4*RSTR + s4)     = *(const uint4*)(vh);
            *(uint4*)(SVh + r4*RSTR + s4 + 8) = *(const uint4*)(vh + 8);
            *(uint4*)(SVl + r4*RSTR + s4)     = *(const uint4*)(vl);
            *(uint4*)(SVl + r4*RSTR + s4 + 8) = *(const uint4*)(vl + 8);
        }
        __syncthreads();

        int iMin = i0 + w*16, iMax = iMin + 15, jMax = j0 + 63;
        if (iMax < j0) continue;

        // ---- S = Q K^T ----
        float s[8][4] = {};
        #pragma unroll
        for (int ks = 0; ks < 4; ks++) {
            int kc = ks*16 + tg*2;
            int ra = (w*16 + g)*RSTR, rb = ra + 8*RSTR;
            uint32_t ah[4], al[4];
            ah[0] = *(const uint32_t*)(SQh + ra + kc);
            ah[1] = *(const uint32_t*)(SQh + rb + kc);
            ah[2] = *(const uint32_t*)(SQh + ra + kc + 8);
            ah[3] = *(const uint32_t*)(SQh + rb + kc + 8);
            al[0] = *(const uint32_t*)(SQl + ra + kc);
            al[1] = *(const uint32_t*)(SQl + rb + kc);
            al[2] = *(const uint32_t*)(SQl + ra + kc + 8);
            al[3] = *(const uint32_t*)(SQl + rb + kc + 8);
            #pragma unroll
            for (int nf = 0; nf < 8; nf++) {
                int n = (nf*8 + g)*RSTR;
                uint32_t bh2[2], bl2[2];
                bh2[0] = *(const uint32_t*)(SKh + n + kc);
                bh2[1] = *(const uint32_t*)(SKh + n + kc + 8);
                bl2[0] = *(const uint32_t*)(SKl + n + kc);
                bl2[1] = *(const uint32_t*)(SKl + n + kc + 8);
                mma16816(s[nf], ah, bh2);
                mma16816(s[nf], ah, bl2);
                mma16816(s[nf], al, bh2);
            }
        }

        // ---- decay / causal mask ----
        if (iMin >= jMax) {
            float tf = exp2f(lg * (float)(i0 - j0));
            float fA = rowA * tf, fB = rowB * tf;
            #pragma unroll
            for (int nf = 0; nf < 8; nf++) {
                float c0 = cf0[nf], c1 = c0 * cstep;
                s[nf][0] *= fA * c0;
                s[nf][1] *= fA * c1;
                s[nf][2] *= fB * c0;
                s[nf][3] *= fB * c1;
            }
        } else {
            int riA = iMin + g, riB = riA + 8;
            #pragma unroll
            for (int nf = 0; nf < 8; nf++) {
                int jg = j0 + nf*8 + tg*2;
                int d0 = riA - jg, d1 = d0 - 1, d2 = riB - jg, d3 = d2 - 1;
                s[nf][0] = (d0 >= 0) ? s[nf][0] * exp2f(lg * (float)d0) : 0.0f;
                s[nf][1] = (d1 >= 0) ? s[nf][1] * exp2f(lg * (float)d1) : 0.0f;
                s[nf][2] = (d2 >= 0) ? s[nf][2] * exp2f(lg * (float)d2) : 0.0f;
                s[nf][3] = (d3 >= 0) ? s[nf][3] * exp2f(lg * (float)d3) : 0.0f;
            }
        }

        // ---- O += S V ----
        #pragma unroll
        for (int ks = 0; ks < 4; ks++) {
            uint32_t sh[4], sl[4];
            cvt_pair(s[2*ks  ][0], s[2*ks  ][1], sh[0], sl[0]);
            cvt_pair(s[2*ks  ][2], s[2*ks  ][3], sh[1], sl[1]);
            cvt_pair(s[2*ks+1][0], s[2*ks+1][1], sh[2], sl[2]);
            cvt_pair(s[2*ks+1][2], s[2*ks+1][3], sh[3], sl[3]);
            int kc = ks*16 + tg*2;
            #pragma unroll
            for (int nd = 0; nd < 8; nd++) {
                int n = (nd*8 + g)*RSTR;
                uint32_t vh[2], vl[2];
                vh[0] = *(const uint32_t*)(SVh + n + kc);
                vh[1] = *(const uint32_t*)(SVh + n + kc + 8);
                vl[0] = *(const uint32_t*)(SVl + n + kc);
                vl[1] = *(const uint32_t*)(SVl + n + kc + 8);
                mma16816(acc_o[nd], sh, vh);
                mma16816(acc_o[nd], sh, vl);
                mma16816(acc_o[nd], sl, vh);
            }
        }
    }

    // ---- write y + GroupNorm partial stats ----
    float lsum = 0.0f, lsq = 0.0f;
    int riA = i0 + w*16 + g;
    #pragma unroll
    for (int nd = 0; nd < 8; nd++) {
        int d0 = nd*8 + tg*2;
        float* d = acc_o[nd];
        lsum += d[0] + d[1] + d[2] + d[3];
        lsq  += d[0]*d[0] + d[1]*d[1] + d[2]*d[2] + d[3]*d[3];
        *(float2*)(g_Y + base + (size_t)riA*DD + d0)     = make_float2(d[0], d[1]);
        *(float2*)(g_Y + base + (size_t)(riA+8)*DD + d0) = make_float2(d[2], d[3]);
    }
    #pragma unroll
    for (int o = 16; o > 0; o >>= 1) {
        lsum += __shfl_down_sync(0xffffffffu, lsum, o);
        lsq  += __shfl_down_sync(0xffffffffu, lsq,  o);
    }
    if (lane == 0) { red[w*2] = lsum; red[w*2 + 1] = lsq; }
    __syncthreads();
    if (tid == 0) {
        float s0 = 0.0f, s1 = 0.0f;
        #pragma unroll
        for (int x = 0; x < 8; x++) { s0 += red[x*2]; s1 += red[x*2 + 1]; }
        g_part[(bh*QT2 + qt)*2 + 0] = s0;
        g_part[(bh*QT2 + qt)*2 + 1] = s1;
    }
}

__global__ void norm_stats_kernel() {
    int i = threadIdx.x;
    if (i < BB*HH) {
        float s = 0.0f, q = 0.0f;
        for (int t = 0; t < QT2; t++) {
            s += g_part[(i*QT2 + t)*2 + 0];
            q += g_part[(i*QT2 + t)*2 + 1];
        }
        float n = (float)(TT * DD);
        float mu = s / n;
        float var = q / n - mu * mu;
        g_norm[i*2 + 0] = mu;
        g_norm[i*2 + 1] = rsqrtf(var + 1e-5f);
    }
}

// GroupNorm apply -> g_Ah/g_Al (pre-split bf16 A operand for the output GEMM)
__global__ void yn_kernel(const float* __restrict__ gnw, const float* __restrict__ gnb) {
    int m = blockIdx.x;
    int k = threadIdx.x * 4;
    int b = m >> 11, t = m & (TT - 1);
    int h = k >> 6, d = k & 63;
    int bh = b*HH + h;
    float mu = g_norm[bh*2 + 0], ri = g_norm[bh*2 + 1];
    float4 y = *(const float4*)(g_Y + ((size_t)bh*TT + t)*DD + d);
    float4 w = *(const float4*)(gnw + k);
    float4 gb = *(const float4*)(gnb + k);
    float o0 = (y.x - mu)*ri*w.x + gb.x;
    float o1 = (y.y - mu)*ri*w.y + gb.y;
    float o2 = (y.z - mu)*ri*w.z + gb.z;
    float o3 = (y.w - mu)*ri*w.w + gb.w;
    uint32_t h0, l0, h1, l1;
    cvt_pair(o0, o1, h0, l0); cvt_pair(o2, o3, h1, l1);
    size_t o = (size_t)m*CC + k;
    *(uint2*)(g_Ah + o) = make_uint2(h0, h1);
    *(uint2*)(g_Al + o) = make_uint2(l0, l1);
}

// ---------------------------------------------------------------------------
extern "C" void kernel_launch(void* const* d_in, const int* in_sizes, int n_in,
                              void* d_out, int out_size) {
    const float* x   = (const float*)d_in[0];
    const float* Wq  = (const float*)d_in[1];
    const float* Wk  = (const float*)d_in[2];
    const float* Wv  = (const float*)d_in[3];
    const float* Wo  = (const float*)d_in[4];
    const float* gnw = (const float*)d_in[5];
    const float* gnb = (const float*)d_in[6];
    float* out = (float*)d_out;

    cudaFuncSetAttribute(gemm_kernel,
                         cudaFuncAttributeMaxDynamicSharedMemorySize, GEMM_SMEM);
    cudaFuncSetAttribute(retention_kernel,
                         cudaFuncAttributeMaxDynamicSharedMemorySize, RET_SMEM);

    const int XN4 = MM*CC/4, WN4 = CC*CC/4;
    dim3 gg(MM/128, CC/128);  // 32 x 8

    split_kernel<<<(XN4 + 255)/256, 256>>>(x, 0, XN4);

    split_kernel<<<(WN4 + 255)/256, 256>>>(Wq, 1, WN4);
    gemm_kernel<<<gg, 256, GEMM_SMEM>>>(nullptr, 0, 0.125f);
    split_kernel<<<(WN4 + 255)/256, 256>>>(Wk, 1, WN4);
    gemm_kernel<<<gg, 256, GEMM_SMEM>>>(nullptr, 1, 1.0f);
    split_kernel<<<(WN4 + 255)/256, 256>>>(Wv, 1, WN4);
    gemm_kernel<<<gg, 256, GEMM_SMEM>>>(nullptr, 2, 1.0f);

    vt_kernel<<<dim3(TT/64, BB*HH), 256>>>();

    retention_kernel<<<dim3(QT2, BB*HH), 256, RET_SMEM>>>();

    norm_stats_kernel<<<1, 32>>>();
    yn_kernel<<<MM, 256>>>(gnw, gnb);

    split_kernel<<<(WN4 + 255)/256, 256>>>(Wo, 1, WN4);
    gemm_kernel<<<gg, 256, GEMM_SMEM>>>(out, 3, 1.0f);
}